// round 14
// baseline (speedup 1.0000x reference)
#include <cuda_runtime.h>

// out[b] = sum_k x[b,k] * S[k],  S[k] = sum_h W[h,k]   (scale 0.5*2.0 == 1.0)
// Role-swap fused pipeline: all 512 CTAs own 8 W-rows AND 8 x-rows and run
// the same staggered schedule, so no CTA ever idles:
//   cs(0) cs(1) [w0]mv(0) cs(2) [w1]mv(1) cs(3) [w2]mv(2) [w3]mv(3)

#define BATCH  4096
#define IN     4096
#define HID    4096
#define NCHUNK 4
#define CK4    256          // float4 columns per chunk (== blockDim)
#define NCTA   512

struct Glob { float S[IN]; int done[NCHUNK]; };
__device__ Glob g;          // zeroed by memset node each replay

__device__ __forceinline__ int ld_acquire(const int* p) {
    int v;
    asm volatile("ld.acquire.gpu.b32 %0, [%1];" : "=r"(v) : "l"(p));
    return v;
}

__global__ void __launch_bounds__(256, 4) fused_kernel(const float* __restrict__ x,
                                                       const float* __restrict__ W,
                                                       float* __restrict__ out) {
    __shared__ float part[8][257];
    const int tid  = threadIdx.x;
    const int lane = tid & 31;
    const int wid  = tid >> 5;
    const int stride4 = IN / 4;

    const float4* Wv = reinterpret_cast<const float4*>(W);
    const float4* xv = reinterpret_cast<const float4*>(x);
    const long rbase = (long)(blockIdx.x * 8) * stride4;   // same 8-row window in W and x

    #pragma unroll
    for (int r = 0; r < 8; r++) part[r][tid] = 0.f;        // thread owns its slot
    // (no barrier needed: only this thread reads/writes part[*][tid] until phase B)

    // ── colsum step for chunk c: sum 8 W-rows into S[chunk c] ──
    auto colsum_step = [&](int c) {
        int k4 = c * CK4 + tid;
        float4 v[8];
        #pragma unroll
        for (int r = 0; r < 8; r++)
            v[r] = __ldcs(&Wv[rbase + (long)r * stride4 + k4]);
        float4 acc = make_float4(0.f, 0.f, 0.f, 0.f);
        #pragma unroll
        for (int r = 0; r < 8; r++) {
            acc.x += v[r].x; acc.y += v[r].y; acc.z += v[r].z; acc.w += v[r].w;
        }
        asm volatile("red.global.add.v4.f32 [%0], {%1, %2, %3, %4};"
                     :: "l"(&g.S[k4 * 4]), "f"(acc.x), "f"(acc.y), "f"(acc.z), "f"(acc.w)
                     : "memory");
        __threadfence();                  // REDG visible before the flag
        __syncthreads();                  // whole CTA done with chunk c
        if (tid == 0) atomicAdd(&g.done[c], 1);
    };

    // ── matvec step for chunk c: 8 x-rows dotted with S[chunk c] ──
    auto matvec_step = [&](int c) {
        if (tid == 0)
            while (ld_acquire(&g.done[c]) < NCTA) __nanosleep(32);
        __syncthreads();                  // S chunk complete + visible to CTA

        int k4 = c * CK4 + tid;
        float4 s4 = reinterpret_cast<const float4*>(g.S)[k4];   // L2-hot
        float4 v[8];
        #pragma unroll
        for (int r = 0; r < 8; r++)
            v[r] = __ldcs(&xv[rbase + (long)r * stride4 + k4]);
        #pragma unroll
        for (int r = 0; r < 8; r++) {
            float p = fmaf(v[r].x, s4.x,
                      fmaf(v[r].y, s4.y,
                      fmaf(v[r].z, s4.z, v[r].w * s4.w)));
            part[r][tid] += p;
        }
    };

    // Staggered schedule (lag ~1.5 chunks absorbs CTA skew).
    colsum_step(0);
    colsum_step(1);
    matvec_step(0);
    colsum_step(2);
    matvec_step(1);
    colsum_step(3);
    matvec_step(2);
    matvec_step(3);

    __syncthreads();

    // Phase B: warp w reduces row w (8 warps, 8 rows). Direct store.
    float s = 0.f;
    #pragma unroll
    for (int j = 0; j < 8; j++)
        s += part[wid][lane + j * 32];
    #pragma unroll
    for (int off = 16; off > 0; off >>= 1)
        s += __shfl_xor_sync(0xFFFFFFFFu, s, off);
    if (lane == 0) out[blockIdx.x * 8 + wid] = s;
}

extern "C" void kernel_launch(void* const* d_in, const int* in_sizes, int n_in,
                              void* d_out, int out_size) {
    const float* x = (const float*)d_in[0];
    const float* W = (const float*)d_in[1];
    float* out = (float*)d_out;

    void* gp = nullptr;
    cudaGetSymbolAddress(&gp, g);
    cudaMemsetAsync(gp, 0, sizeof(Glob));   // zeros S and done[]

    fused_kernel<<<NCTA, 256>>>(x, W, out);
}

// round 15
// speedup vs baseline: 1.1118x; 1.1118x over previous
#include <cuda_runtime.h>

// out[b] = sum_k x[b,k] * S[k],  S[k] = sum_h W[h,k]   (scale 0.5*2.0 == 1.0)
// Fused static-split pipeline with shared warm-up:
//   phase 0: ALL 512 CTAs colsum W-chunk0 (8 rows each)  -> no idle fill
//   then:    CTAs 0-255 colsum chunks 1-3 (no waits)
//            CTAs 256-511 matvec chunks 0-3 (wait on doneW[c] only)

#define BATCH  4096
#define IN     4096
#define HID    4096
#define NCHUNK 4
#define CK4    256          // float4 columns per chunk (== blockDim)
#define NCTA   512
#define NCS    256          // colsum-role CTAs (also = #matvec-role CTAs)

struct Glob { float S[IN]; int doneW[NCHUNK]; };
__device__ Glob g;          // zeroed by memset node each replay

__device__ __forceinline__ int ld_acquire(const int* p) {
    int v;
    asm volatile("ld.acquire.gpu.b32 %0, [%1];" : "=r"(v) : "l"(p));
    return v;
}

__device__ __forceinline__ void redg_v4(float* dst, float4 a) {
    asm volatile("red.global.add.v4.f32 [%0], {%1, %2, %3, %4};"
                 :: "l"(dst), "f"(a.x), "f"(a.y), "f"(a.z), "f"(a.w) : "memory");
}

__global__ void __launch_bounds__(256, 4) fused_kernel(const float* __restrict__ x,
                                                       const float* __restrict__ W,
                                                       float* __restrict__ out) {
    __shared__ float part[16][257];
    const int tid  = threadIdx.x;
    const int lane = tid & 31;
    const int wid  = tid >> 5;
    const int stride4 = IN / 4;

    const float4* Wv = reinterpret_cast<const float4*>(W);
    const float4* xv = reinterpret_cast<const float4*>(x);

    // ── Phase 0: every CTA colsums its 8 W-rows of chunk 0 ──
    {
        long rbase = (long)(blockIdx.x * 8) * stride4;
        int k4 = tid;                                     // chunk 0 columns
        float4 v[8];
        #pragma unroll
        for (int r = 0; r < 8; r++)
            v[r] = __ldcs(&Wv[rbase + (long)r * stride4 + k4]);
        float4 acc = make_float4(0.f, 0.f, 0.f, 0.f);
        #pragma unroll
        for (int r = 0; r < 8; r++) {
            acc.x += v[r].x; acc.y += v[r].y; acc.z += v[r].z; acc.w += v[r].w;
        }
        redg_v4(&g.S[k4 * 4], acc);
        __threadfence();
        __syncthreads();
        if (tid == 0) atomicAdd(&g.doneW[0], 1);
    }

    if (blockIdx.x < NCS) {
        // ── colsum role: chunks 1..3, 16 rows each, NO waits ──
        long rbase = (long)(blockIdx.x * 16) * stride4;
        for (int c = 1; c < NCHUNK; c++) {
            int k4 = c * CK4 + tid;
            float4 acc = make_float4(0.f, 0.f, 0.f, 0.f);
            #pragma unroll
            for (int gq = 0; gq < 2; gq++) {
                float4 v[8];
                #pragma unroll
                for (int r = 0; r < 8; r++)
                    v[r] = __ldcs(&Wv[rbase + (long)(gq * 8 + r) * stride4 + k4]);
                #pragma unroll
                for (int r = 0; r < 8; r++) {
                    acc.x += v[r].x; acc.y += v[r].y;
                    acc.z += v[r].z; acc.w += v[r].w;
                }
            }
            redg_v4(&g.S[k4 * 4], acc);
            __threadfence();
            __syncthreads();
            if (tid == 0) atomicAdd(&g.doneW[c], 1);
        }
    } else {
        // ── matvec role: 16 x-rows, chunks 0..3, waits on doneW[c] ──
        int m = blockIdx.x - NCS;
        long rbase = (long)(m * 16) * stride4;

        #pragma unroll
        for (int r = 0; r < 16; r++) part[r][tid] = 0.f;  // thread owns slot

        for (int c = 0; c < NCHUNK; c++) {
            int need = (c == 0) ? NCTA : NCS;
            if (tid == 0)
                while (ld_acquire(&g.doneW[c]) < need) __nanosleep(32);
            __syncthreads();              // S chunk complete + visible

            int k4 = c * CK4 + tid;
            float4 s4 = reinterpret_cast<const float4*>(g.S)[k4];   // L2-hot

            #pragma unroll
            for (int gq = 0; gq < 2; gq++) {
                float4 v[8];
                #pragma unroll
                for (int r = 0; r < 8; r++)
                    v[r] = __ldcs(&xv[rbase + (long)(gq * 8 + r) * stride4 + k4]);
                #pragma unroll
                for (int r = 0; r < 8; r++) {
                    float p = fmaf(v[r].x, s4.x,
                              fmaf(v[r].y, s4.y,
                              fmaf(v[r].z, s4.z, v[r].w * s4.w)));
                    part[gq * 8 + r][tid] += p;
                }
            }
        }
        __syncthreads();

        // Deferred reduce: warp w handles rows w and w+8. Direct store.
        #pragma unroll
        for (int rr = 0; rr < 2; rr++) {
            int r = wid + rr * 8;
            float s = 0.f;
            #pragma unroll
            for (int j = 0; j < 8; j++)
                s += part[r][lane + j * 32];
            #pragma unroll
            for (int off = 16; off > 0; off >>= 1)
                s += __shfl_xor_sync(0xFFFFFFFFu, s, off);
            if (lane == 0) out[m * 16 + r] = s;
        }
    }
}

extern "C" void kernel_launch(void* const* d_in, const int* in_sizes, int n_in,
                              void* d_out, int out_size) {
    const float* x = (const float*)d_in[0];
    const float* W = (const float*)d_in[1];
    float* out = (float*)d_out;

    void* gp = nullptr;
    cudaGetSymbolAddress(&gp, g);
    cudaMemsetAsync(gp, 0, sizeof(Glob));   // zeros S and doneW[]

    fused_kernel<<<NCTA, 256>>>(x, W, out);
}